// round 3
// baseline (speedup 1.0000x reference)
#include <cuda_runtime.h>
#include <cstdint>

#define NN 23
#define IK 529                 // NN*NN
#define TT 12
#define BB 16                  // batches per block
#define CB 8                   // batches per chunk
#define NCH 2                  // chunks (all prefetched up front)
#define ECHUNK (CB * IK)       // 4232 elements per chunk
#define NTHR 736               // 23 warps: warp = i, lane = k

typedef unsigned long long ull;

__device__ __forceinline__ void cp_async4(void* smem_dst, const void* gmem_src) {
    uint32_t s = (uint32_t)__cvta_generic_to_shared(smem_dst);
    asm volatile("cp.async.ca.shared.global [%0], [%1], 4;\n"
                 :: "r"(s), "l"(gmem_src));
}
__device__ __forceinline__ void cp_async_commit() {
    asm volatile("cp.async.commit_group;\n" ::: "memory");
}
template <int Ngrp>
__device__ __forceinline__ void cp_async_wait() {
    asm volatile("cp.async.wait_group %0;\n" :: "n"(Ngrp) : "memory");
}

// packed f32x2 helpers (sm_100a+)
__device__ __forceinline__ ull fma2(ull a, ull b, ull c) {
    ull d;
    asm("fma.rn.f32x2 %0, %1, %2, %3;" : "=l"(d) : "l"(a), "l"(b), "l"(c));
    return d;
}
__device__ __forceinline__ ull bcast2(float x) {
    ull r;
    asm("mov.b64 %0, {%1, %1};" : "=l"(r) : "f"(x));
    return r;
}
__device__ __forceinline__ void unpack2(ull v, float& lo, float& hi) {
    asm("mov.b64 {%0, %1}, %2;" : "=f"(lo), "=f"(hi) : "l"(v));
}

__global__ __launch_bounds__(NTHR, 1)
void resgat_kernel(const float* __restrict__ fx,
                   const int* __restrict__ adj,
                   const float* __restrict__ W1,
                   const float* __restrict__ W2,
                   const float* __restrict__ a_in,
                   const float* __restrict__ a_out,
                   float* __restrict__ out) {
    // d_s[chunk][ik][batch]: 32B rows -> one LDS.128 grabs 4 batches
    __shared__ __align__(32) float d_s[NCH][IK][CB];

    const int tid  = threadIdx.x;
    const int wid  = tid >> 5;            // warp = i (0..22)
    const int lane = tid & 31;            // lane = k
    const int b0   = blockIdx.x * BB;

    // ---- front-load ALL gathers (2 commit groups, max MLP immediately) ----
#pragma unroll
    for (int c = 0; c < NCH; c++) {
#pragma unroll
        for (int it = 0; it < 6; it++) {
            int t = tid + it * NTHR;
            if (t < ECHUNK) {
                int b_l = t / IK;
                int ik  = t - b_l * IK;
                // flow_x[(b0 + c*CB + b_l), ik, TT-1]; note (b*IK+ik)*TT = (b0*IK + g)*TT
                const float* src =
                    fx + ((size_t)b0 * IK + (size_t)c * ECHUNK + t) * TT + (TT - 1);
                cp_async4(&d_s[c][ik][b_l], src);
            }
        }
        cp_async_commit();
    }

    // ---- fold coefficients inline (L2-cached reads, hidden under cp.async) ----
    const int i = wid;
    const bool act = (lane < NN);
    const int k = act ? lane : 0;
    const int ikidx = i * NN + k;

    float si  = a_in[ikidx * 2 + 0] + a_in[ikidx * 2 + 1];
    float yi0 = a_in[ikidx * 2 + 0] / si;
    float yi1 = a_in[ikidx * 2 + 1] / si;
    float so  = a_out[ikidx * 2 + 0] + a_out[ikidx * 2 + 1];
    float yo0 = a_out[ikidx * 2 + 0] / so;
    float yo1 = a_out[ikidx * 2 + 1] / so;

    float a1[NN], a2[NN];
    {
        float w1[NN], w2[NN], msk[NN];
        float mn1 = 0.0f, mn2 = 0.0f;   // torch.where(min > 0, 0, min) => min(.,0)
#pragma unroll
        for (int m = 0; m < NN; m++) {
            w1[m]  = W1[ikidx * NN + m];
            w2[m]  = W2[ikidx * NN + m];
            msk[m] = (m == k || adj[k * NN + m] != 0) ? 1.0f : 0.0f;
            mn1 = fminf(mn1, w1[m]);
            mn2 = fminf(mn2, w2[m]);
        }
        float s1 = 0.0f, s2 = 0.0f;
#pragma unroll
        for (int m = 0; m < NN; m++) {
            w1[m] = (w1[m] - mn1) * msk[m];
            w2[m] = (w2[m] - mn2) * msk[m];
            s1 += w1[m];
            s2 += w2[m];
        }
        float sc1 = yo1 * yi0 / s1;
        float sc2 = yo1 * yi1 / s2;
#pragma unroll
        for (int m = 0; m < NN; m++) {
            a1[m] = w1[m] * sc1;
            a2[m] = w2[m] * sc2 + ((m == k) ? yo0 : 0.0f);  // residual folds to diag
        }
    }

    // ---- per-chunk compute: out[b,i,k] = sum_m a1[m]*d[b,m,i] + a2[m]*d[b,i,m] ----
#pragma unroll
    for (int c = 0; c < NCH; c++) {
        if (c == 0) cp_async_wait<1>(); else cp_async_wait<0>();
        __syncthreads();

        ull acc0 = 0ull, acc1 = 0ull, acc2 = 0ull, acc3 = 0ull;  // 4 batch-pairs
#pragma unroll
        for (int m = 0; m < NN; m++) {
            ull a1p = bcast2(a1[m]);
            ull a2p = bcast2(a2[m]);
            // uniform (broadcast) 16B shared loads: 2 per operand row
            const ulonglong2* dc = (const ulonglong2*)&d_s[c][m * NN + i][0];
            const ulonglong2* dr = (const ulonglong2*)&d_s[c][i * NN + m][0];
            ulonglong2 c01 = dc[0], c23 = dc[1];
            ulonglong2 r01 = dr[0], r23 = dr[1];
            acc0 = fma2(a1p, c01.x, acc0);  acc0 = fma2(a2p, r01.x, acc0);
            acc1 = fma2(a1p, c01.y, acc1);  acc1 = fma2(a2p, r01.y, acc1);
            acc2 = fma2(a1p, c23.x, acc2);  acc2 = fma2(a2p, r23.x, acc2);
            acc3 = fma2(a1p, c23.y, acc3);  acc3 = fma2(a2p, r23.y, acc3);
        }

        if (act) {
            int bb = b0 + c * CB;
            float lo, hi;
            size_t o = (size_t)bb * IK + ikidx;
            unpack2(acc0, lo, hi); out[o]          = lo; out[o + IK]     = hi;
            unpack2(acc1, lo, hi); out[o + 2 * IK] = lo; out[o + 3 * IK] = hi;
            unpack2(acc2, lo, hi); out[o + 4 * IK] = lo; out[o + 5 * IK] = hi;
            unpack2(acc3, lo, hi); out[o + 6 * IK] = lo; out[o + 7 * IK] = hi;
        }
        // no trailing sync: buffers are not reused
    }
}

extern "C" void kernel_launch(void* const* d_in, const int* in_sizes, int n_in,
                              void* d_out, int out_size) {
    const float* fx    = (const float*)d_in[0];
    const int*   adj   = (const int*)d_in[1];
    const float* W1    = (const float*)d_in[2];
    const float* W2    = (const float*)d_in[3];
    const float* a_in  = (const float*)d_in[4];
    const float* a_out = (const float*)d_in[5];
    float* out = (float*)d_out;

    int B = in_sizes[0] / (IK * TT);   // 8192
    resgat_kernel<<<B / BB, NTHR>>>(fx, adj, W1, W2, a_in, a_out, out);
}